// round 1
// baseline (speedup 1.0000x reference)
#include <cuda_runtime.h>
#include <math.h>

#define BB 32
#define H0 161
#define W0 1024
#define C1 32
#define H1 81
#define W1 512
#define C2 32
#define H2 41
#define W2 512
#define EPSV 1e-5f

// Scratch: masked conv1 output (x1) and transposed conv2 weights.
__device__ float g_x1[BB * C1 * H1 * W1];          // 32*32*81*512 floats
__device__ float g_w2t[21 * 32 * 32 * 12];         // [kh][ic][oc][12] (kw padded 11->12)

// ---------------------------------------------------------------------------
// Kernel 0: transpose conv2 weights [oc][ic][kh][kw] -> [kh][ic][oc][12]
// ---------------------------------------------------------------------------
__global__ void transpose_w2_kernel(const float* __restrict__ w2) {
    int i = blockIdx.x * 256 + threadIdx.x;
    const int total = 21 * 32 * 32 * 12;
    if (i >= total) return;
    int kw = i % 12;
    int t = i / 12;
    int oc = t % 32;
    t /= 32;
    int ic = t % 32;
    int kh = t / 32;
    float v = 0.f;
    if (kw < 11) v = w2[((oc * 32 + ic) * 21 + kh) * 11 + kw];
    g_w2t[i] = v;
}

// ---------------------------------------------------------------------------
// Kernel 1: conv1 (1->32ch, 41x11, stride 2x2, pad 20x5) + bias + BN + clip
//           + time mask, writes g_x1.
// One thread = one (b, h1, w), register-tiles all 32 output channels.
// ---------------------------------------------------------------------------
__global__ void __launch_bounds__(128) conv1_kernel(
    const float* __restrict__ in, const int* __restrict__ seq,
    const float* __restrict__ w1, const float* __restrict__ b1,
    const float* __restrict__ g1, const float* __restrict__ be1,
    const float* __restrict__ m1, const float* __restrict__ v1)
{
    extern __shared__ float sm[];
    float* ws = sm;                  // [41][11][32] = 14432 floats
    float* sa = sm + 41 * 11 * 32;   // [32] BN scale
    float* sc = sa + 32;             // [32] BN shift (bias folded)

    int tid = threadIdx.x;
    for (int i = tid; i < 41 * 11 * 32; i += 128) {
        int oc = i / 451;
        int r  = i % 451;
        ws[r * 32 + oc] = w1[i];
    }
    if (tid < 32) {
        float a = g1[tid] / sqrtf(v1[tid] + EPSV);
        sa[tid] = a;
        sc[tid] = b1[tid] * a + be1[tid] - m1[tid] * a;
    }
    __syncthreads();

    int b  = blockIdx.z;
    int h1 = blockIdx.y;
    int w  = blockIdx.x * 128 + tid;
    int len1 = (seq[b] - 1) / 2 + 1;

    float acc[32];
#pragma unroll
    for (int o = 0; o < 32; o++) acc[o] = 0.f;

    bool valid = (w < len1);
    if (valid) {
        const float* ib = in + b * H0 * W0;
        for (int kh = 0; kh < 41; kh++) {
            int ih = h1 * 2 + kh - 20;
            if ((unsigned)ih >= H0) continue;
            const float* row  = ib + ih * W0;
            const float* wrow = ws + kh * 11 * 32;
#pragma unroll
            for (int kw = 0; kw < 11; kw++) {
                int iw = w * 2 + kw - 5;
                if ((unsigned)iw >= W0) continue;
                float xv = row[iw];
#pragma unroll
                for (int o = 0; o < 32; o++)
                    acc[o] = fmaf(xv, wrow[kw * 32 + o], acc[o]);
            }
        }
    }

#pragma unroll
    for (int o = 0; o < 32; o++) {
        float y = 0.f;
        if (valid) {
            y = acc[o] * sa[o] + sc[o];
            y = fminf(fmaxf(y, 0.f), 20.f);
        }
        g_x1[((b * 32 + o) * H1 + h1) * W1 + w] = y;
    }
}

// ---------------------------------------------------------------------------
// Kernel 2: conv2 (32->32ch, 21x11, stride 2x1, pad 10x5) + bias + BN + clip
//           + time mask -> out.
// Block: (b, 4 h2 rows, 64 w). 256 threads = 32 oc x 8 wgroups; each thread
// owns 4x8 outputs for its oc. kh streamed; per-kh smem: input rows + weight
// slice. Fully-masked w-tiles early-out.
// ---------------------------------------------------------------------------
__global__ void __launch_bounds__(256) conv2_kernel(
    const int* __restrict__ seq,
    const float* __restrict__ b2, const float* __restrict__ g2,
    const float* __restrict__ be2, const float* __restrict__ m2,
    const float* __restrict__ v2,
    float* __restrict__ out)
{
    extern __shared__ float sm[];
    float* in_s = sm;                 // [4][32][76] = 9728 floats
    float* ws_s = sm + 4 * 32 * 76;   // [32ic][32oc][12] = 12288 floats

    int tid = threadIdx.x;
    int oc = tid >> 3;
    int wg = tid & 7;
    int b   = blockIdx.z;
    int h2b = blockIdx.y * 4;
    int w0  = blockIdx.x * 64;
    int len1 = (seq[b] - 1) / 2 + 1;

    float acc[4][8];
#pragma unroll
    for (int r = 0; r < 4; r++)
#pragma unroll
        for (int j = 0; j < 8; j++) acc[r][j] = 0.f;

    bool anyw = (w0 < len1);   // uniform across block
    if (anyw) {
        for (int kh = 0; kh < 21; kh++) {
            // weight slice (coalesced: pre-transposed, contiguous)
            const float* wsrc = g_w2t + kh * 12288;
            for (int i = tid; i < 12288; i += 256) ws_s[i] = wsrc[i];
            // input rows for the 4 h2 positions of this block
            for (int i = tid; i < 4 * 32 * 76; i += 256) {
                int l = i % 76;
                int t = i / 76;
                int ic = t % 32;
                int r  = t / 32;
                int ih = (h2b + r) * 2 + kh - 10;
                int iw = w0 - 5 + l;
                float v = 0.f;
                if (l < 74 && (unsigned)ih < H1 && (unsigned)iw < W1)
                    v = g_x1[((b * 32 + ic) * H1 + ih) * W1 + iw];
                in_s[i] = v;
            }
            __syncthreads();

            for (int ic = 0; ic < 32; ic++) {
                float wr[11];
#pragma unroll
                for (int kw = 0; kw < 11; kw++)
                    wr[kw] = ws_s[(ic * 32 + oc) * 12 + kw];
#pragma unroll
                for (int r = 0; r < 4; r++) {
                    float iv[18];
                    const float* ip = in_s + (r * 32 + ic) * 76 + wg * 8;
#pragma unroll
                    for (int j = 0; j < 18; j++) iv[j] = ip[j];
#pragma unroll
                    for (int j = 0; j < 8; j++)
#pragma unroll
                        for (int kw = 0; kw < 11; kw++)
                            acc[r][j] = fmaf(iv[j + kw], wr[kw], acc[r][j]);
                }
            }
            __syncthreads();
        }
    }

    float a = g2[oc] / sqrtf(v2[oc] + EPSV);
    float c = b2[oc] * a + be2[oc] - m2[oc] * a;
#pragma unroll
    for (int r = 0; r < 4; r++) {
        int h2 = h2b + r;
        if (h2 >= H2) continue;
#pragma unroll
        for (int j = 0; j < 8; j++) {
            int w = w0 + wg * 8 + j;
            float y = 0.f;
            if (w < len1) {
                y = acc[r][j] * a + c;
                y = fminf(fmaxf(y, 0.f), 20.f);
            }
            out[((b * 32 + oc) * H2 + h2) * W2 + w] = y;
        }
    }
}

// ---------------------------------------------------------------------------
// Kernel 3: write new sequence lengths (as float) past the tensor, if the
// harness output buffer includes them.
// ---------------------------------------------------------------------------
__global__ void tail_kernel(const int* __restrict__ seq, float* __restrict__ out,
                            int base) {
    int i = threadIdx.x;
    if (i < BB) {
        int len1 = (seq[i] - 1) / 2 + 1;
        out[base + i] = (float)len1;
    }
}

extern "C" void kernel_launch(void* const* d_in, const int* in_sizes, int n_in,
                              void* d_out, int out_size) {
    const float* inputs = (const float*)d_in[0];
    const int*   seq    = (const int*)d_in[1];
    const float* w1 = (const float*)d_in[2];
    const float* b1 = (const float*)d_in[3];
    const float* g1 = (const float*)d_in[4];
    const float* be1 = (const float*)d_in[5];
    const float* m1 = (const float*)d_in[6];
    const float* v1 = (const float*)d_in[7];
    const float* w2 = (const float*)d_in[8];
    const float* b2 = (const float*)d_in[9];
    const float* g2 = (const float*)d_in[10];
    const float* be2 = (const float*)d_in[11];
    const float* m2 = (const float*)d_in[12];
    const float* v2 = (const float*)d_in[13];
    float* out = (float*)d_out;

    const int smem1 = (41 * 11 * 32 + 64) * 4;            // 57,984 B
    const int smem2 = (4 * 32 * 76 + 32 * 32 * 12) * 4;   // 88,064 B
    cudaFuncSetAttribute(conv1_kernel, cudaFuncAttributeMaxDynamicSharedMemorySize, smem1);
    cudaFuncSetAttribute(conv2_kernel, cudaFuncAttributeMaxDynamicSharedMemorySize, smem2);

    // 0: weight transpose for conv2
    {
        int total = 21 * 32 * 32 * 12;
        transpose_w2_kernel<<<(total + 255) / 256, 256>>>(w2);
    }
    // 1: conv1 fused -> g_x1
    {
        dim3 grid(W1 / 128, H1, BB);
        conv1_kernel<<<grid, 128, smem1>>>(inputs, seq, w1, b1, g1, be1, m1, v1);
    }
    // 2: conv2 fused -> out
    {
        dim3 grid(W2 / 64, (H2 + 3) / 4, BB);
        conv2_kernel<<<grid, 256, smem2>>>(seq, b2, g2, be2, m2, v2, out);
    }
    // 3: sequence lengths tail (only if the output buffer includes them)
    const int xsize = BB * C2 * H2 * W2;
    if (out_size >= xsize + BB) {
        tail_kernel<<<1, 32>>>(seq, out, xsize);
    }
}

// round 3
// speedup vs baseline: 2.2918x; 2.2918x over previous
#include <cuda_runtime.h>
#include <math.h>
#include <stdint.h>

#define BB 32
#define H0 161
#define W0 1024
#define H1 81
#define W1 512
#define H2 41
#define W2 512
#define EPSV 1e-5f

#define ASTRIDE 36
#define AOFF_F 256                         // floats: BN consts live in [0,64)
#define BOFF_F (AOFF_F + 522 * ASTRIDE)    // 19048
#define SM2_FLOATS (BOFF_F + 11 * 32 * ASTRIDE)  // 31720 floats = 126880 B

// x1 scratch, channels-last: [b][h1][w][ic], ic=32 contiguous (tf32-rounded)
__device__ float g_x1[BB * H1 * W1 * 32];
// conv2 weights: [kh][kw][oc][36 pad], tf32-rounded
__device__ float g_w2t[21 * 11 * 32 * ASTRIDE];

__device__ __forceinline__ float tf32_rna(float v) {
    uint32_t u;
    asm("cvt.rna.tf32.f32 %0, %1;" : "=r"(u) : "f"(v));
    return __uint_as_float(u);
}

__device__ __forceinline__ void mma_tf32(float* d, const uint32_t* a,
                                         const uint32_t* bfr) {
    asm volatile(
        "mma.sync.aligned.m16n8k8.row.col.f32.tf32.tf32.f32 "
        "{%0,%1,%2,%3}, {%4,%5,%6,%7}, {%8,%9}, {%0,%1,%2,%3};"
        : "+f"(d[0]), "+f"(d[1]), "+f"(d[2]), "+f"(d[3])
        : "r"(a[0]), "r"(a[1]), "r"(a[2]), "r"(a[3]),
          "r"(bfr[0]), "r"(bfr[1]));
}

// ---------------------------------------------------------------------------
// Kernel 0: rearrange conv2 weights [oc][ic][kh][kw] -> [kh][kw][oc][36],
// tf32-rounded.
// ---------------------------------------------------------------------------
__global__ void transpose_w2_kernel(const float* __restrict__ w2) {
    int i = blockIdx.x * 256 + threadIdx.x;
    const int total = 21 * 11 * 32 * 32;
    if (i >= total) return;
    int ic = i & 31;
    int t = i >> 5;
    int oc = t & 31;
    t >>= 5;
    int kw = t % 11;
    int kh = t / 11;
    float v = w2[((oc * 32 + ic) * 21 + kh) * 11 + kw];
    g_w2t[((kh * 11 + kw) * 32 + oc) * ASTRIDE + ic] = tf32_rna(v);
}

// ---------------------------------------------------------------------------
// Kernel 1: conv1 (1->32, 41x11, s(2,2), p(20,5)) + bias + BN + clip + mask
//           -> g_x1 channels-last, tf32-rounded.
// ---------------------------------------------------------------------------
__global__ void __launch_bounds__(128) conv1_kernel(
    const float* __restrict__ in, const int* __restrict__ seq,
    const float* __restrict__ w1, const float* __restrict__ b1,
    const float* __restrict__ g1, const float* __restrict__ be1,
    const float* __restrict__ m1, const float* __restrict__ v1)
{
    extern __shared__ float sm[];
    float* ws = sm;                  // [41][11][32]
    float* sa = sm + 41 * 11 * 32;
    float* sc = sa + 32;

    int tid = threadIdx.x;
    for (int i = tid; i < 41 * 11 * 32; i += 128) {
        int oc = i / 451;
        int r  = i % 451;
        ws[r * 32 + oc] = w1[i];
    }
    if (tid < 32) {
        float a = g1[tid] * rsqrtf(v1[tid] + EPSV);
        sa[tid] = a;
        sc[tid] = b1[tid] * a + be1[tid] - m1[tid] * a;
    }
    __syncthreads();

    int b  = blockIdx.z;
    int h1 = blockIdx.y;
    int w  = blockIdx.x * 128 + tid;
    int len1 = (seq[b] - 1) / 2 + 1;

    float acc[32];
#pragma unroll
    for (int o = 0; o < 32; o++) acc[o] = 0.f;

    bool valid = (w < len1);
    if (valid) {
        const float* ib = in + (size_t)b * H0 * W0;
        for (int kh = 0; kh < 41; kh++) {
            int ih = h1 * 2 + kh - 20;
            if ((unsigned)ih >= H0) continue;
            const float* row  = ib + (size_t)ih * W0;
            const float* wrow = ws + kh * 11 * 32;
#pragma unroll
            for (int kw = 0; kw < 11; kw++) {
                int iw = w * 2 + kw - 5;
                if ((unsigned)iw >= W0) continue;
                float xv = row[iw];
#pragma unroll
                for (int o = 0; o < 32; o++)
                    acc[o] = fmaf(xv, wrow[kw * 32 + o], acc[o]);
            }
        }
    }

    float res[32];
#pragma unroll
    for (int o = 0; o < 32; o++) {
        float y = 0.f;
        if (valid) {
            y = acc[o] * sa[o] + sc[o];
            y = fminf(fmaxf(y, 0.f), 20.f);
            y = tf32_rna(y);
        }
        res[o] = y;
    }
    float4* dst = (float4*)(g_x1 + ((size_t)(b * H1 + h1) * W1 + w) * 32);
#pragma unroll
    for (int q = 0; q < 8; q++)
        dst[q] = make_float4(res[4*q], res[4*q+1], res[4*q+2], res[4*q+3]);
}

// ---------------------------------------------------------------------------
// Kernel 2: conv2 via mma.sync tf32 implicit GEMM, (kh,kw)-decomposed.
// CTA = (b,h2): 8 warps x 64 pixels. A slab: x1 row, 522 rows x 36 floats.
// B slab: weights [kw][oc][36] for current kh. Mask early-out per m-tile.
// ---------------------------------------------------------------------------
__global__ void __launch_bounds__(256, 1) conv2_mma_kernel(
    const int* __restrict__ seq,
    const float* __restrict__ b2, const float* __restrict__ g2,
    const float* __restrict__ be2, const float* __restrict__ m2,
    const float* __restrict__ v2,
    float* __restrict__ out)
{
    extern __shared__ float sm[];
    int tid = threadIdx.x, wid = tid >> 5, lane = tid & 31;
    int gid = lane >> 2, tg = lane & 3;
    int b = blockIdx.z, h2 = blockIdx.y;
    int len1 = (seq[b] - 1) / 2 + 1;
    int npix = min(512, len1);
    int act  = min(512, (npix + 15) & ~15);
    int arows = min(522, act + 10);

    if (tid < 32) {
        float a = g2[tid] * rsqrtf(v2[tid] + EPSV);
        sm[tid]      = a;
        sm[32 + tid] = b2[tid] * a + be2[tid] - m2[tid] * a;
    }

    float acc[4][4][4];
#pragma unroll
    for (int mt = 0; mt < 4; mt++)
#pragma unroll
        for (int nt = 0; nt < 4; nt++)
#pragma unroll
            for (int r = 0; r < 4; r++) acc[mt][nt][r] = 0.f;

    for (int kh = 0; kh < 21; kh++) {
        int ih = 2 * h2 + kh - 10;
        if ((unsigned)ih >= H1) continue;
        __syncthreads();
        // A slab
        {
            const float4* asrc =
                (const float4*)(g_x1 + (size_t)(b * H1 + ih) * W1 * 32);
            for (int i = tid; i < arows * 8; i += 256) {
                int row = i >> 3, q = i & 7;
                int w = row - 5;
                float4 v = make_float4(0.f, 0.f, 0.f, 0.f);
                if ((unsigned)w < W1) v = asrc[(w << 3) + q];
                *(float4*)(sm + AOFF_F + row * ASTRIDE + q * 4) = v;
            }
        }
        // B slab (contiguous)
        {
            const float4* bsrc = (const float4*)(g_w2t + kh * 11 * 32 * ASTRIDE);
            float4* bdst = (float4*)(sm + BOFF_F);
            for (int i = tid; i < 11 * 32 * 9; i += 256) bdst[i] = bsrc[i];
        }
        __syncthreads();

        for (int kw = 0; kw < 11; kw++) {
            // B fragments: oc = nt*8+gid, k = tg + ks*8 (+4)
            uint32_t bf[4][4][2];
            const float* bp = sm + BOFF_F + (kw * 32 + gid) * ASTRIDE + tg;
#pragma unroll
            for (int nt = 0; nt < 4; nt++)
#pragma unroll
                for (int ks = 0; ks < 4; ks++) {
                    bf[nt][ks][0] = __float_as_uint(bp[nt * 8 * ASTRIDE + ks * 8]);
                    bf[nt][ks][1] = __float_as_uint(bp[nt * 8 * ASTRIDE + ks * 8 + 4]);
                }
#pragma unroll
            for (int mt = 0; mt < 4; mt++) {
                int pb = wid * 64 + mt * 16;
                if (pb >= npix) continue;   // warp-uniform mask early-out
                const float* ap = sm + AOFF_F + (pb + gid + kw) * ASTRIDE + tg;
                uint32_t af[4][4];
#pragma unroll
                for (int ks = 0; ks < 4; ks++) {
                    af[ks][0] = __float_as_uint(ap[ks * 8]);
                    af[ks][1] = __float_as_uint(ap[8 * ASTRIDE + ks * 8]);
                    af[ks][2] = __float_as_uint(ap[ks * 8 + 4]);
                    af[ks][3] = __float_as_uint(ap[8 * ASTRIDE + ks * 8 + 4]);
                }
#pragma unroll
                for (int nt = 0; nt < 4; nt++)
#pragma unroll
                    for (int ks = 0; ks < 4; ks++)
                        mma_tf32(acc[mt][nt], af[ks], bf[nt][ks]);
            }
        }
    }

    // Epilogue: BN + clip + mask. D fragment: row=pixel, col=oc.
    const float* sa = sm;
    const float* sc = sm + 32;
#pragma unroll
    for (int mt = 0; mt < 4; mt++) {
        int p0 = wid * 64 + mt * 16 + gid;
        int p1 = p0 + 8;
#pragma unroll
        for (int nt = 0; nt < 4; nt++) {
            int oc0 = nt * 8 + 2 * tg;
            int oc1 = oc0 + 1;
            float a0 = sa[oc0], c0 = sc[oc0];
            float a1 = sa[oc1], c1 = sc[oc1];
            float* o00 = out + ((size_t)(b * 32 + oc0) * H2 + h2) * W2;
            float* o01 = out + ((size_t)(b * 32 + oc1) * H2 + h2) * W2;
            float y0 = (p0 < len1) ? fminf(fmaxf(acc[mt][nt][0] * a0 + c0, 0.f), 20.f) : 0.f;
            float y1 = (p0 < len1) ? fminf(fmaxf(acc[mt][nt][1] * a1 + c1, 0.f), 20.f) : 0.f;
            float y2 = (p1 < len1) ? fminf(fmaxf(acc[mt][nt][2] * a0 + c0, 0.f), 20.f) : 0.f;
            float y3 = (p1 < len1) ? fminf(fmaxf(acc[mt][nt][3] * a1 + c1, 0.f), 20.f) : 0.f;
            o00[p0] = y0;
            o01[p0] = y1;
            o00[p1] = y2;
            o01[p1] = y3;
        }
    }
}

// ---------------------------------------------------------------------------
// Kernel 3: sequence lengths tail (as float) past the tensor, if present.
// ---------------------------------------------------------------------------
__global__ void tail_kernel(const int* __restrict__ seq, float* __restrict__ out,
                            int base) {
    int i = threadIdx.x;
    if (i < BB) {
        int len1 = (seq[i] - 1) / 2 + 1;
        out[base + i] = (float)len1;
    }
}

extern "C" void kernel_launch(void* const* d_in, const int* in_sizes, int n_in,
                              void* d_out, int out_size) {
    const float* inputs = (const float*)d_in[0];
    const int*   seq    = (const int*)d_in[1];
    const float* w1 = (const float*)d_in[2];
    const float* b1 = (const float*)d_in[3];
    const float* g1 = (const float*)d_in[4];
    const float* be1 = (const float*)d_in[5];
    const float* m1 = (const float*)d_in[6];
    const float* v1 = (const float*)d_in[7];
    const float* w2 = (const float*)d_in[8];
    const float* b2 = (const float*)d_in[9];
    const float* g2 = (const float*)d_in[10];
    const float* be2 = (const float*)d_in[11];
    const float* m2 = (const float*)d_in[12];
    const float* v2 = (const float*)d_in[13];
    float* out = (float*)d_out;

    const int smem1 = (41 * 11 * 32 + 64) * 4;
    const int smem2 = SM2_FLOATS * 4;
    cudaFuncSetAttribute(conv1_kernel, cudaFuncAttributeMaxDynamicSharedMemorySize, smem1);
    cudaFuncSetAttribute(conv2_mma_kernel, cudaFuncAttributeMaxDynamicSharedMemorySize, smem2);

    {
        int total = 21 * 11 * 32 * 32;
        transpose_w2_kernel<<<(total + 255) / 256, 256>>>(w2);
    }
    {
        dim3 grid(W1 / 128, H1, BB);
        conv1_kernel<<<grid, 128, smem1>>>(inputs, seq, w1, b1, g1, be1, m1, v1);
    }
    {
        dim3 grid(1, H2, BB);
        conv2_mma_kernel<<<grid, 256, smem2>>>(seq, b2, g2, be2, m2, v2, out);
    }
    const int xsize = BB * 32 * H2 * W2;
    if (out_size >= xsize + BB) {
        tail_kernel<<<1, 32>>>(seq, out, xsize);
    }
}

// round 4
// speedup vs baseline: 2.8236x; 1.2321x over previous
#include <cuda_runtime.h>
#include <cuda_fp16.h>
#include <math.h>
#include <stdint.h>

#define BB 32
#define H0 161
#define W0 1024
#define H1 81
#define W1 512
#define H2 41
#define W2 512
#define EPSV 1e-5f

// x1 scratch: channels-last fp16 [b][h1][w][ic], 32 halves (64B) per pixel
__device__ __half g_x1h[BB * H1 * W1 * 32];
// conv2 weights fp16: [kh][kw][oc][40 pad]
__device__ __half g_w2h[21 * 11 * 32 * 40];

// ---- conv2 smem layout (bytes) ----
#define HDR_B 256
#define A_STRIDE_B 80
#define A_ROWS 522
#define ABUF_B (A_ROWS * A_STRIDE_B)   // 41760
#define BBUF_B (11 * 32 * 40 * 2)      // 28160
#define A0_OFF HDR_B
#define A1_OFF (A0_OFF + ABUF_B)
#define B0_OFF (A1_OFF + ABUF_B)
#define B1_OFF (B0_OFF + BBUF_B)
#define SM2_BYTES (B1_OFF + BBUF_B)    // 140096

__device__ __forceinline__ uint32_t smem_u32(const void* p) {
    uint32_t a;
    asm("{ .reg .u64 t; cvta.to.shared.u64 t, %1; cvt.u32.u64 %0, t; }"
        : "=r"(a) : "l"(p));
    return a;
}

__device__ __forceinline__ void cp16(uint32_t dst, const void* src) {
    asm volatile("cp.async.ca.shared.global [%0], [%1], 16;"
                 :: "r"(dst), "l"(src) : "memory");
}
__device__ __forceinline__ void cp_commit() {
    asm volatile("cp.async.commit_group;" ::: "memory");
}
__device__ __forceinline__ void cp_wait1() {
    asm volatile("cp.async.wait_group 1;" ::: "memory");
}
__device__ __forceinline__ void cp_wait0() {
    asm volatile("cp.async.wait_group 0;" ::: "memory");
}

__device__ __forceinline__ void ldm_x4(uint32_t* a, uint32_t addr) {
    asm volatile("ldmatrix.sync.aligned.m8n8.x4.shared.b16 {%0,%1,%2,%3}, [%4];"
                 : "=r"(a[0]), "=r"(a[1]), "=r"(a[2]), "=r"(a[3]) : "r"(addr));
}

__device__ __forceinline__ void mma_f16(float* d, const uint32_t* a,
                                        const uint32_t* b) {
    asm volatile(
        "mma.sync.aligned.m16n8k16.row.col.f32.f16.f16.f32 "
        "{%0,%1,%2,%3}, {%4,%5,%6,%7}, {%8,%9}, {%0,%1,%2,%3};"
        : "+f"(d[0]), "+f"(d[1]), "+f"(d[2]), "+f"(d[3])
        : "r"(a[0]), "r"(a[1]), "r"(a[2]), "r"(a[3]), "r"(b[0]), "r"(b[1]));
}

// ---------------------------------------------------------------------------
// Kernel 0: w2 [oc][ic][kh][kw] -> g_w2h [kh][kw][oc][40] fp16 (pad zeros)
// ---------------------------------------------------------------------------
__global__ void transpose_w2_kernel(const float* __restrict__ w2) {
    int i = blockIdx.x * 256 + threadIdx.x;
    const int total = 21 * 11 * 32 * 40;
    if (i >= total) return;
    int ic = i % 40;
    int t = i / 40;
    int oc = t & 31;
    t >>= 5;
    int kw = t % 11;
    int kh = t / 11;
    float v = (ic < 32) ? w2[((oc * 32 + ic) * 21 + kh) * 11 + kw] : 0.f;
    g_w2h[i] = __float2half_rn(v);
}

// ---------------------------------------------------------------------------
// Kernel 1: conv1 (1->32, 41x11, s(2,2), p(20,5)) + BN + clip + mask -> x1h.
// CTA = (b, h1, 64 w). 128 thr = 8 wq x 16 ocp. Weights in regs per kh,
// input rows in smem (loaded once), register-cached via float4.
// ---------------------------------------------------------------------------
#define IN_STRIDE 140
#define C1_SM_FLOATS (41 * 11 * 32 + 41 * IN_STRIDE + 64)

__global__ void __launch_bounds__(128) conv1_kernel(
    const float* __restrict__ in, const int* __restrict__ seq,
    const float* __restrict__ w1, const float* __restrict__ b1,
    const float* __restrict__ g1, const float* __restrict__ be1,
    const float* __restrict__ m1, const float* __restrict__ v1)
{
    extern __shared__ float sm[];
    float* ws   = sm;                        // [kh][kw][32 oc]
    float* in_s = sm + 41 * 11 * 32;         // [41][140]
    float* sa   = in_s + 41 * IN_STRIDE;
    float* sc   = sa + 32;

    int tid = threadIdx.x;
    int b  = blockIdx.z;
    int h1 = blockIdx.y;
    int w0 = blockIdx.x * 64;
    int len1 = (seq[b] - 1) / 2 + 1;

    for (int i = tid; i < 41 * 11 * 32; i += 128) {
        int oc = i / 451;
        int r  = i % 451;
        ws[r * 32 + oc] = w1[i];
    }
    if (tid < 32) {
        float a = g1[tid] * rsqrtf(v1[tid] + EPSV);
        sa[tid] = a;
        sc[tid] = b1[tid] * a + be1[tid] - m1[tid] * a;
    }
    {
        const float* ib = in + (size_t)b * H0 * W0;
        for (int i = tid; i < 41 * IN_STRIDE; i += 128) {
            int kh = i / IN_STRIDE, t = i % IN_STRIDE;
            int ih = 2 * h1 + kh - 20;
            int gi = 2 * w0 - 5 + t;
            float v = 0.f;
            if ((unsigned)ih < H0 && (unsigned)gi < W0)
                v = ib[(size_t)ih * W0 + gi];
            in_s[i] = v;
        }
    }
    __syncthreads();

    int ocp = tid & 15;
    int wq  = tid >> 4;
    __half* dst0 = g_x1h + ((size_t)(b * H1 + h1) * W1 + w0 + wq * 8) * 32 + 2 * ocp;

    if (w0 >= len1) {
#pragma unroll
        for (int j = 0; j < 8; j++)
            *(__half2*)(dst0 + (size_t)j * 32) = __half2half2(__float2half(0.f));
        return;
    }

    float2 acc[8];
#pragma unroll
    for (int j = 0; j < 8; j++) acc[j] = make_float2(0.f, 0.f);

#pragma unroll 1
    for (int kh = 0; kh < 41; kh++) {
        const float* wb = ws + kh * 352 + 2 * ocp;
        float2 wk[11];
#pragma unroll
        for (int kw = 0; kw < 11; kw++)
            wk[kw] = *(const float2*)(wb + kw * 32);
        float iv[28];
        const float* ip = in_s + kh * IN_STRIDE + 16 * wq;
#pragma unroll
        for (int q = 0; q < 7; q++) {
            float4 v = *(const float4*)(ip + 4 * q);
            iv[4*q] = v.x; iv[4*q+1] = v.y; iv[4*q+2] = v.z; iv[4*q+3] = v.w;
        }
#pragma unroll
        for (int kw = 0; kw < 11; kw++)
#pragma unroll
            for (int j = 0; j < 8; j++) {
                float a = iv[2 * j + kw];
                acc[j].x = fmaf(a, wk[kw].x, acc[j].x);
                acc[j].y = fmaf(a, wk[kw].y, acc[j].y);
            }
    }

    float a0 = sa[2 * ocp], c0 = sc[2 * ocp];
    float a1 = sa[2 * ocp + 1], c1 = sc[2 * ocp + 1];
#pragma unroll
    for (int j = 0; j < 8; j++) {
        int w = w0 + wq * 8 + j;
        float y0 = 0.f, y1 = 0.f;
        if (w < len1) {
            y0 = fminf(fmaxf(acc[j].x * a0 + c0, 0.f), 20.f);
            y1 = fminf(fmaxf(acc[j].y * a1 + c1, 0.f), 20.f);
        }
        *(__half2*)(dst0 + (size_t)j * 32) =
            __halves2half2(__float2half_rn(y0), __float2half_rn(y1));
    }
}

// ---------------------------------------------------------------------------
// Kernel 2: conv2 fp16 mma implicit GEMM, cp.async double-buffered over kh.
// CTA = (b,h2): 8 warps x 64 px. A: [522 rows x 80B] fp16; B: [kw][oc][40].
// ---------------------------------------------------------------------------
__global__ void __launch_bounds__(256, 1) conv2_mma_kernel(
    const int* __restrict__ seq,
    const float* __restrict__ b2, const float* __restrict__ g2,
    const float* __restrict__ be2, const float* __restrict__ m2,
    const float* __restrict__ v2,
    float* __restrict__ out)
{
    extern __shared__ char smc[];
    uint32_t sb = smem_u32(smc);
    float* hdr = (float*)smc;
    int tid = threadIdx.x, wid = tid >> 5, lane = tid & 31;
    int gid = lane >> 2, tg = lane & 3;
    int b = blockIdx.z, h2 = blockIdx.y;
    int len1 = (seq[b] - 1) / 2 + 1;
    int npix = min(512, len1);
    int act  = min(512, (npix + 15) & ~15);
    int arows = min(A_ROWS, act + 10);
    int rmax = min(arows, 517);

    if (tid < 32) {
        float a = g2[tid] * rsqrtf(v2[tid] + EPSV);
        hdr[tid]      = a;
        hdr[32 + tid] = b2[tid] * a + be2[tid] - m2[tid] * a;
    }
    // zero boundary rows (w<0, w>=512) of both A buffers
    for (int i = tid; i < 100; i += 256) {
        int bi = i / 50, j = i % 50;
        int r = j / 5; r = (r < 5) ? r : r + 512;
        *(float4*)(smc + (bi ? A1_OFF : A0_OFF) + r * A_STRIDE_B + (j % 5) * 16) =
            make_float4(0.f, 0.f, 0.f, 0.f);
    }

    int khL = max(0, 10 - 2 * h2);
    int khH = min(20, 90 - 2 * h2);

    const __half* xbase = g_x1h + (size_t)(b * H1) * W1 * 32;

    // --- async loaders ---
    auto load_A = [&](int kh, uint32_t aoff) {
        int ih = 2 * h2 + kh - 10;
        const __half* src = xbase + (size_t)ih * W1 * 32;
        int chunks = (rmax - 5) * 4;
        for (int i = tid; i < chunks; i += 256) {
            int r = 5 + (i >> 2), c = i & 3;
            cp16(sb + aoff + r * A_STRIDE_B + c * 16, src + (size_t)(r - 5) * 32 + c * 8);
        }
    };
    auto load_B = [&](int kh, uint32_t boff) {
        const __half* src = g_w2h + (size_t)kh * (11 * 32 * 40);
        for (int i = tid; i < 1760; i += 256)
            cp16(sb + boff + i * 16, src + i * 8);
    };

    float acc[4][4][4];
#pragma unroll
    for (int mt = 0; mt < 4; mt++)
#pragma unroll
        for (int nt = 0; nt < 4; nt++)
#pragma unroll
            for (int r = 0; r < 4; r++) acc[mt][nt][r] = 0.f;

    load_A(khL, A0_OFF);
    load_B(khL, B0_OFF);
    cp_commit();

    uint32_t lane_a = (uint32_t)((lane & 15) * A_STRIDE_B + (lane >> 4) * 16);
    int buf = 0;

    for (int kh = khL; kh <= khH; kh++) {
        if (kh < khH) {
            load_A(kh + 1, buf ? A0_OFF : A1_OFF);
            load_B(kh + 1, buf ? B0_OFF : B1_OFF);
            cp_commit();
            cp_wait1();
        } else {
            cp_wait0();
        }
        __syncthreads();

        uint32_t aoff = buf ? A1_OFF : A0_OFF;
        const __half* bp0 = (const __half*)(smc + (buf ? B1_OFF : B0_OFF));

        for (int kw = 0; kw < 11; kw++) {
            uint32_t bf[4][2][2];
            const __half* bp = bp0 + kw * 32 * 40;
#pragma unroll
            for (int nt = 0; nt < 4; nt++)
#pragma unroll
                for (int ks = 0; ks < 2; ks++) {
                    const __half* q = bp + (nt * 8 + gid) * 40 + ks * 16 + 2 * tg;
                    bf[nt][ks][0] = *(const uint32_t*)q;
                    bf[nt][ks][1] = *(const uint32_t*)(q + 8);
                }
#pragma unroll
            for (int mt = 0; mt < 4; mt++) {
                int pb = wid * 64 + mt * 16;
                if (pb >= npix) continue;
                uint32_t abase = sb + aoff + (uint32_t)(pb + kw) * A_STRIDE_B + lane_a;
#pragma unroll
                for (int ks = 0; ks < 2; ks++) {
                    uint32_t af[4];
                    ldm_x4(af, abase + ks * 32);
#pragma unroll
                    for (int nt = 0; nt < 4; nt++)
                        mma_f16(acc[mt][nt], af, bf[nt][ks]);
                }
            }
        }
        __syncthreads();
        buf ^= 1;
    }

    // Epilogue: BN + clip + mask (D frag: c0/c1 row gid cols 2tg,2tg+1; c2/c3 row gid+8)
    const float* sa = hdr;
    const float* sc = hdr + 32;
#pragma unroll
    for (int mt = 0; mt < 4; mt++) {
        int p0 = wid * 64 + mt * 16 + gid;
        int p1 = p0 + 8;
#pragma unroll
        for (int nt = 0; nt < 4; nt++) {
            int oc0 = nt * 8 + 2 * tg;
            int oc1 = oc0 + 1;
            float a0 = sa[oc0], c0 = sc[oc0];
            float a1 = sa[oc1], c1 = sc[oc1];
            float* o0 = out + ((size_t)(b * 32 + oc0) * H2 + h2) * W2;
            float* o1 = out + ((size_t)(b * 32 + oc1) * H2 + h2) * W2;
            o0[p0] = (p0 < len1) ? fminf(fmaxf(acc[mt][nt][0] * a0 + c0, 0.f), 20.f) : 0.f;
            o1[p0] = (p0 < len1) ? fminf(fmaxf(acc[mt][nt][1] * a1 + c1, 0.f), 20.f) : 0.f;
            o0[p1] = (p1 < len1) ? fminf(fmaxf(acc[mt][nt][2] * a0 + c0, 0.f), 20.f) : 0.f;
            o1[p1] = (p1 < len1) ? fminf(fmaxf(acc[mt][nt][3] * a1 + c1, 0.f), 20.f) : 0.f;
        }
    }
}

// ---------------------------------------------------------------------------
// Kernel 3: sequence-length tail (floats) past the tensor, if present.
// ---------------------------------------------------------------------------
__global__ void tail_kernel(const int* __restrict__ seq, float* __restrict__ out,
                            int base) {
    int i = threadIdx.x;
    if (i < BB) {
        int len1 = (seq[i] - 1) / 2 + 1;
        out[base + i] = (float)len1;
    }
}

extern "C" void kernel_launch(void* const* d_in, const int* in_sizes, int n_in,
                              void* d_out, int out_size) {
    const float* inputs = (const float*)d_in[0];
    const int*   seq    = (const int*)d_in[1];
    const float* w1 = (const float*)d_in[2];
    const float* b1 = (const float*)d_in[3];
    const float* g1 = (const float*)d_in[4];
    const float* be1 = (const float*)d_in[5];
    const float* m1 = (const float*)d_in[6];
    const float* v1 = (const float*)d_in[7];
    const float* w2 = (const float*)d_in[8];
    const float* b2 = (const float*)d_in[9];
    const float* g2 = (const float*)d_in[10];
    const float* be2 = (const float*)d_in[11];
    const float* m2 = (const float*)d_in[12];
    const float* v2 = (const float*)d_in[13];
    float* out = (float*)d_out;

    const int smem1 = C1_SM_FLOATS * 4;
    cudaFuncSetAttribute(conv1_kernel, cudaFuncAttributeMaxDynamicSharedMemorySize, smem1);
    cudaFuncSetAttribute(conv2_mma_kernel, cudaFuncAttributeMaxDynamicSharedMemorySize, SM2_BYTES);

    {
        int total = 21 * 11 * 32 * 40;
        transpose_w2_kernel<<<(total + 255) / 256, 256>>>(w2);
    }
    {
        dim3 grid(W1 / 64, H1, BB);
        conv1_kernel<<<grid, 128, smem1>>>(inputs, seq, w1, b1, g1, be1, m1, v1);
    }
    {
        dim3 grid(1, H2, BB);
        conv2_mma_kernel<<<grid, 256, SM2_BYTES>>>(seq, b2, g2, be2, m2, v2, out);
    }
    const int xsize = BB * 32 * H2 * W2;
    if (out_size >= xsize + BB) {
        tail_kernel<<<1, 32>>>(seq, out, xsize);
    }
}

// round 5
// speedup vs baseline: 6.9719x; 2.4691x over previous
#include <cuda_runtime.h>
#include <cuda_fp16.h>
#include <math.h>
#include <stdint.h>

#define BB 32
#define H0 161
#define W0 1024
#define H1 81
#define W1 512
#define H2 41
#define W2 512
#define EPSV 1e-5f

// x1 scratch: channels-last fp16 [b][h1][w][ic]
__device__ __half g_x1h[BB * H1 * W1 * 32];
// conv2 weights fp16: [kh][kw][oc][40 pad]
__device__ __half g_w2h[21 * 11 * 32 * 40];
// conv1 input, fp16, shifted rows: [b][ih][t], t in [0,1056), S[t]=in[t-5]
#define C1_ROW_H 1056
__device__ __half g_in_h[BB * H0 * C1_ROW_H];
// conv1 weights fp16: [kh][oc][18], k=kw (0..10), pad 11..17 = 0
__device__ __half g_w1h[41 * 32 * 18];

// ---------------------------------------------------------------------------
__device__ __forceinline__ uint32_t smem_u32(const void* p) {
    uint32_t a;
    asm("{ .reg .u64 t; cvta.to.shared.u64 t, %1; cvt.u32.u64 %0, t; }"
        : "=r"(a) : "l"(p));
    return a;
}
__device__ __forceinline__ void cp16(uint32_t dst, const void* src) {
    asm volatile("cp.async.ca.shared.global [%0], [%1], 16;"
                 :: "r"(dst), "l"(src) : "memory");
}
__device__ __forceinline__ void cp_commit() {
    asm volatile("cp.async.commit_group;" ::: "memory");
}
__device__ __forceinline__ void cp_wait1() {
    asm volatile("cp.async.wait_group 1;" ::: "memory");
}
__device__ __forceinline__ void cp_wait0() {
    asm volatile("cp.async.wait_group 0;" ::: "memory");
}
__device__ __forceinline__ void ldm_x4(uint32_t* a, uint32_t addr) {
    asm volatile("ldmatrix.sync.aligned.m8n8.x4.shared.b16 {%0,%1,%2,%3}, [%4];"
                 : "=r"(a[0]), "=r"(a[1]), "=r"(a[2]), "=r"(a[3]) : "r"(addr));
}
__device__ __forceinline__ void mma_f16(float* d, const uint32_t* a,
                                        const uint32_t* b) {
    asm volatile(
        "mma.sync.aligned.m16n8k16.row.col.f32.f16.f16.f32 "
        "{%0,%1,%2,%3}, {%4,%5,%6,%7}, {%8,%9}, {%0,%1,%2,%3};"
        : "+f"(d[0]), "+f"(d[1]), "+f"(d[2]), "+f"(d[3])
        : "r"(a[0]), "r"(a[1]), "r"(a[2]), "r"(a[3]), "r"(b[0]), "r"(b[1]));
}

// ---------------------------------------------------------------------------
// Prep kernels
// ---------------------------------------------------------------------------
__global__ void prep_in_kernel(const float* __restrict__ in) {
    int i = blockIdx.x * 256 + threadIdx.x;
    const int total = BB * H0 * C1_ROW_H;
    if (i >= total) return;
    int t = i % C1_ROW_H;
    int r = i / C1_ROW_H;           // b*H0 + ih
    int s = t - 5;
    float v = 0.f;
    if ((unsigned)s < W0) v = in[(size_t)r * W0 + s];
    g_in_h[i] = __float2half_rn(v);
}

__global__ void prep_w1_kernel(const float* __restrict__ w1) {
    int i = blockIdx.x * 256 + threadIdx.x;
    const int total = 41 * 32 * 18;
    if (i >= total) return;
    int k = i % 18;
    int t = i / 18;
    int oc = t & 31;
    int kh = t >> 5;
    float v = (k < 11) ? w1[oc * 451 + kh * 11 + k] : 0.f;
    g_w1h[i] = __float2half_rn(v);
}

__global__ void transpose_w2_kernel(const float* __restrict__ w2) {
    int i = blockIdx.x * 256 + threadIdx.x;
    const int total = 21 * 11 * 32 * 40;
    if (i >= total) return;
    int ic = i % 40;
    int t = i / 40;
    int oc = t & 31;
    t >>= 5;
    int kw = t % 11;
    int kh = t / 11;
    float v = (ic < 32) ? w2[((oc * 32 + ic) * 21 + kh) * 11 + kw] : 0.f;
    g_w2h[i] = __float2half_rn(v);
}

// ---------------------------------------------------------------------------
// Kernel 1: conv1 via fp16 mma, kh-decomposed (K = 16 taps, kw>=11 zero).
// CTA = (h1, b): 8 warps x 64 px. w1 slab loaded once; rows double-buffered.
// ---------------------------------------------------------------------------
#define C1_HDR 256
#define C1_W_OFF C1_HDR
#define C1_W_BYTES (41 * 32 * 18 * 2)        // 47232
#define C1_R_OFF (C1_W_OFF + C1_W_BYTES)     // 47488
#define C1_ROWB (C1_ROW_H * 2)               // 2112
#define C1_SM_BYTES (C1_R_OFF + 2 * C1_ROWB) // 51712

__global__ void __launch_bounds__(256, 2) conv1_mma_kernel(
    const int* __restrict__ seq,
    const float* __restrict__ b1, const float* __restrict__ g1,
    const float* __restrict__ be1, const float* __restrict__ m1,
    const float* __restrict__ v1)
{
    extern __shared__ char smc[];
    uint32_t sb = smem_u32(smc);
    float* hdr = (float*)smc;
    int tid = threadIdx.x, wid = tid >> 5, lane = tid & 31;
    int gid = lane >> 2, tg = lane & 3;
    int h1 = blockIdx.x, b = blockIdx.y;
    int len1 = (seq[b] - 1) / 2 + 1;
    int npix = min(512, len1);

    if (tid < 32) {
        float a = g1[tid] * rsqrtf(v1[tid] + EPSV);
        hdr[tid]      = a;
        hdr[32 + tid] = b1[tid] * a + be1[tid] - m1[tid] * a;
    }
    // w1 slab (group 0)
    for (int i = tid; i < C1_W_BYTES / 16; i += 256)
        cp16(sb + C1_W_OFF + i * 16, (const char*)g_w1h + i * 16);
    cp_commit();

    int khL = max(0, 20 - 2 * h1);
    int khH = min(40, 180 - 2 * h1);
    const __half* inb = g_in_h + (size_t)(b * H0) * C1_ROW_H;

    auto load_row = [&](int kh, int buf) {
        const __half* src = inb + (size_t)(2 * h1 + kh - 20) * C1_ROW_H;
        uint32_t dst = sb + C1_R_OFF + buf * C1_ROWB;
        for (int i = tid; i < C1_ROWB / 16; i += 256)
            cp16(dst + i * 16, src + i * 8);
    };

    float acc[4][4][4];
#pragma unroll
    for (int mt = 0; mt < 4; mt++)
#pragma unroll
        for (int nt = 0; nt < 4; nt++)
#pragma unroll
            for (int r = 0; r < 4; r++) acc[mt][nt][r] = 0.f;

    load_row(khL, 0);
    cp_commit();
    int buf = 0;

    for (int kh = khL; kh <= khH; kh++) {
        if (kh < khH) {
            load_row(kh + 1, buf ^ 1);
            cp_commit();
            cp_wait1();
        } else {
            cp_wait0();
        }
        __syncthreads();

        // B frags: B[oc=nt*8+gid][k=2tg..+1, 2tg+8..+9]
        uint32_t bf[4][2];
        const char* wk = smc + C1_W_OFF + kh * (32 * 18 * 2);
#pragma unroll
        for (int nt = 0; nt < 4; nt++) {
            const char* q = wk + (nt * 8 + gid) * 36 + tg * 4;
            bf[nt][0] = *(const uint32_t*)q;
            bf[nt][1] = *(const uint32_t*)(q + 16);
        }
        const char* arow = smc + C1_R_OFF + buf * C1_ROWB;
#pragma unroll
        for (int mt = 0; mt < 4; mt++) {
            int pb = wid * 64 + mt * 16;
            if (pb >= npix) continue;
            const char* ab = arow + 4 * (pb + gid + tg);
            uint32_t af[4];
            af[0] = *(const uint32_t*)(ab);
            af[1] = *(const uint32_t*)(ab + 32);
            af[2] = *(const uint32_t*)(ab + 16);
            af[3] = *(const uint32_t*)(ab + 48);
#pragma unroll
            for (int nt = 0; nt < 4; nt++)
                mma_f16(acc[mt][nt], af, bf[nt]);
        }
        __syncthreads();
        buf ^= 1;
    }

    // Epilogue: BN + clip + mask -> x1h channels-last (half2 per oc pair)
    const float* sa = hdr;
    const float* sc = hdr + 32;
    __half* xb = g_x1h + (size_t)(b * H1 + h1) * W1 * 32;
#pragma unroll
    for (int mt = 0; mt < 4; mt++) {
        int p0 = wid * 64 + mt * 16 + gid;
        int p1 = p0 + 8;
#pragma unroll
        for (int nt = 0; nt < 4; nt++) {
            int oc0 = nt * 8 + 2 * tg;
            float a0 = sa[oc0], c0 = sc[oc0];
            float a1 = sa[oc0 + 1], c1 = sc[oc0 + 1];
            float y0 = 0.f, y1 = 0.f, y2 = 0.f, y3 = 0.f;
            if (p0 < len1) {
                y0 = fminf(fmaxf(acc[mt][nt][0] * a0 + c0, 0.f), 20.f);
                y1 = fminf(fmaxf(acc[mt][nt][1] * a1 + c1, 0.f), 20.f);
            }
            if (p1 < len1) {
                y2 = fminf(fmaxf(acc[mt][nt][2] * a0 + c0, 0.f), 20.f);
                y3 = fminf(fmaxf(acc[mt][nt][3] * a1 + c1, 0.f), 20.f);
            }
            *(__half2*)(xb + (size_t)p0 * 32 + oc0) =
                __halves2half2(__float2half_rn(y0), __float2half_rn(y1));
            *(__half2*)(xb + (size_t)p1 * 32 + oc0) =
                __halves2half2(__float2half_rn(y2), __float2half_rn(y3));
        }
    }
}

// ---------------------------------------------------------------------------
// Kernel 2: conv2 fp16 mma implicit GEMM (unchanged from R4, proven).
// ---------------------------------------------------------------------------
#define HDR_B 256
#define A_STRIDE_B 80
#define A_ROWS 522
#define ABUF_B (A_ROWS * A_STRIDE_B)
#define BBUF_B (11 * 32 * 40 * 2)
#define A0_OFF HDR_B
#define A1_OFF (A0_OFF + ABUF_B)
#define B0_OFF (A1_OFF + ABUF_B)
#define B1_OFF (B0_OFF + BBUF_B)
#define SM2_BYTES (B1_OFF + BBUF_B)

__global__ void __launch_bounds__(256, 1) conv2_mma_kernel(
    const int* __restrict__ seq,
    const float* __restrict__ b2, const float* __restrict__ g2,
    const float* __restrict__ be2, const float* __restrict__ m2,
    const float* __restrict__ v2,
    float* __restrict__ out)
{
    extern __shared__ char smc[];
    uint32_t sb = smem_u32(smc);
    float* hdr = (float*)smc;
    int tid = threadIdx.x, wid = tid >> 5, lane = tid & 31;
    int gid = lane >> 2, tg = lane & 3;
    int b = blockIdx.z, h2 = blockIdx.y;
    int len1 = (seq[b] - 1) / 2 + 1;
    int npix = min(512, len1);
    int act  = min(512, (npix + 15) & ~15);
    int arows = min(A_ROWS, act + 10);
    int rmax = min(arows, 517);

    if (tid < 32) {
        float a = g2[tid] * rsqrtf(v2[tid] + EPSV);
        hdr[tid]      = a;
        hdr[32 + tid] = b2[tid] * a + be2[tid] - m2[tid] * a;
    }
    for (int i = tid; i < 100; i += 256) {
        int bi = i / 50, j = i % 50;
        int r = j / 5; r = (r < 5) ? r : r + 512;
        *(float4*)(smc + (bi ? A1_OFF : A0_OFF) + r * A_STRIDE_B + (j % 5) * 16) =
            make_float4(0.f, 0.f, 0.f, 0.f);
    }

    int khL = max(0, 10 - 2 * h2);
    int khH = min(20, 90 - 2 * h2);
    const __half* xbase = g_x1h + (size_t)(b * H1) * W1 * 32;

    auto load_A = [&](int kh, uint32_t aoff) {
        int ih = 2 * h2 + kh - 10;
        const __half* src = xbase + (size_t)ih * W1 * 32;
        int chunks = (rmax - 5) * 4;
        for (int i = tid; i < chunks; i += 256) {
            int r = 5 + (i >> 2), c = i & 3;
            cp16(sb + aoff + r * A_STRIDE_B + c * 16, src + (size_t)(r - 5) * 32 + c * 8);
        }
    };
    auto load_B = [&](int kh, uint32_t boff) {
        const __half* src = g_w2h + (size_t)kh * (11 * 32 * 40);
        for (int i = tid; i < 1760; i += 256)
            cp16(sb + boff + i * 16, src + i * 8);
    };

    float acc[4][4][4];
#pragma unroll
    for (int mt = 0; mt < 4; mt++)
#pragma unroll
        for (int nt = 0; nt < 4; nt++)
#pragma unroll
            for (int r = 0; r < 4; r++) acc[mt][nt][r] = 0.f;

    load_A(khL, A0_OFF);
    load_B(khL, B0_OFF);
    cp_commit();

    uint32_t lane_a = (uint32_t)((lane & 15) * A_STRIDE_B + (lane >> 4) * 16);
    int buf = 0;

    for (int kh = khL; kh <= khH; kh++) {
        if (kh < khH) {
            load_A(kh + 1, buf ? A0_OFF : A1_OFF);
            load_B(kh + 1, buf ? B0_OFF : B1_OFF);
            cp_commit();
            cp_wait1();
        } else {
            cp_wait0();
        }
        __syncthreads();

        uint32_t aoff = buf ? A1_OFF : A0_OFF;
        const __half* bp0 = (const __half*)(smc + (buf ? B1_OFF : B0_OFF));

        for (int kw = 0; kw < 11; kw++) {
            uint32_t bf[4][2][2];
            const __half* bp = bp0 + kw * 32 * 40;
#pragma unroll
            for (int nt = 0; nt < 4; nt++)
#pragma unroll
                for (int ks = 0; ks < 2; ks++) {
                    const __half* q = bp + (nt * 8 + gid) * 40 + ks * 16 + 2 * tg;
                    bf[nt][ks][0] = *(const uint32_t*)q;
                    bf[nt][ks][1] = *(const uint32_t*)(q + 8);
                }
#pragma unroll
            for (int mt = 0; mt < 4; mt++) {
                int pb = wid * 64 + mt * 16;
                if (pb >= npix) continue;
                uint32_t abase = sb + aoff + (uint32_t)(pb + kw) * A_STRIDE_B + lane_a;
#pragma unroll
                for (int ks = 0; ks < 2; ks++) {
                    uint32_t af[4];
                    ldm_x4(af, abase + ks * 32);
#pragma unroll
                    for (int nt = 0; nt < 4; nt++)
                        mma_f16(acc[mt][nt], af, bf[nt][ks]);
                }
            }
        }
        __syncthreads();
        buf ^= 1;
    }

    const float* sa = hdr;
    const float* sc = hdr + 32;
#pragma unroll
    for (int mt = 0; mt < 4; mt++) {
        int p0 = wid * 64 + mt * 16 + gid;
        int p1 = p0 + 8;
#pragma unroll
        for (int nt = 0; nt < 4; nt++) {
            int oc0 = nt * 8 + 2 * tg;
            int oc1 = oc0 + 1;
            float a0 = sa[oc0], c0 = sc[oc0];
            float a1 = sa[oc1], c1 = sc[oc1];
            float* o0 = out + ((size_t)(b * 32 + oc0) * H2 + h2) * W2;
            float* o1 = out + ((size_t)(b * 32 + oc1) * H2 + h2) * W2;
            o0[p0] = (p0 < len1) ? fminf(fmaxf(acc[mt][nt][0] * a0 + c0, 0.f), 20.f) : 0.f;
            o1[p0] = (p0 < len1) ? fminf(fmaxf(acc[mt][nt][1] * a1 + c1, 0.f), 20.f) : 0.f;
            o0[p1] = (p1 < len1) ? fminf(fmaxf(acc[mt][nt][2] * a0 + c0, 0.f), 20.f) : 0.f;
            o1[p1] = (p1 < len1) ? fminf(fmaxf(acc[mt][nt][3] * a1 + c1, 0.f), 20.f) : 0.f;
        }
    }
}

// ---------------------------------------------------------------------------
__global__ void tail_kernel(const int* __restrict__ seq, float* __restrict__ out,
                            int base) {
    int i = threadIdx.x;
    if (i < BB) {
        int len1 = (seq[i] - 1) / 2 + 1;
        out[base + i] = (float)len1;
    }
}

extern "C" void kernel_launch(void* const* d_in, const int* in_sizes, int n_in,
                              void* d_out, int out_size) {
    const float* inputs = (const float*)d_in[0];
    const int*   seq    = (const int*)d_in[1];
    const float* w1 = (const float*)d_in[2];
    const float* b1 = (const float*)d_in[3];
    const float* g1 = (const float*)d_in[4];
    const float* be1 = (const float*)d_in[5];
    const float* m1 = (const float*)d_in[6];
    const float* v1 = (const float*)d_in[7];
    const float* w2 = (const float*)d_in[8];
    const float* b2 = (const float*)d_in[9];
    const float* g2 = (const float*)d_in[10];
    const float* be2 = (const float*)d_in[11];
    const float* m2 = (const float*)d_in[12];
    const float* v2 = (const float*)d_in[13];
    float* out = (float*)d_out;

    cudaFuncSetAttribute(conv1_mma_kernel, cudaFuncAttributeMaxDynamicSharedMemorySize, C1_SM_BYTES);
    cudaFuncSetAttribute(conv2_mma_kernel, cudaFuncAttributeMaxDynamicSharedMemorySize, SM2_BYTES);

    {
        int total = BB * H0 * C1_ROW_H;
        prep_in_kernel<<<(total + 255) / 256, 256>>>(inputs);
    }
    {
        int total = 41 * 32 * 18;
        prep_w1_kernel<<<(total + 255) / 256, 256>>>(w1);
    }
    {
        int total = 21 * 11 * 32 * 40;
        transpose_w2_kernel<<<(total + 255) / 256, 256>>>(w2);
    }
    {
        dim3 grid(H1, BB);
        conv1_mma_kernel<<<grid, 256, C1_SM_BYTES>>>(seq, b1, g1, be1, m1, v1);
    }
    {
        dim3 grid(1, H2, BB);
        conv2_mma_kernel<<<grid, 256, SM2_BYTES>>>(seq, b2, g2, be2, m2, v2, out);
    }
    const int xsize = BB * 32 * H2 * W2;
    if (out_size >= xsize + BB) {
        tail_kernel<<<1, 32>>>(seq, out, xsize);
    }
}

// round 7
// speedup vs baseline: 8.2494x; 1.1832x over previous
#include <cuda_runtime.h>
#include <cuda_fp16.h>
#include <math.h>
#include <stdint.h>

#define BB 32
#define H0 161
#define W0 1024
#define H1 81
#define W1 512
#define H2 41
#define W2 512
#define EPSV 1e-5f

// x1 scratch: channels-last fp16 [b][h1][w][ic]
__device__ __half g_x1h[BB * H1 * W1 * 32];
// conv2 weights fp16: [kh][kw][oc][40 pad]
__device__ __half g_w2h[21 * 11 * 32 * 40];
// conv1 input, fp16, shifted rows: [b][ih][t], t in [0,1056), S[t]=in[t-5]
#define C1_ROW_H 1056
__device__ __half g_in_h[BB * H0 * C1_ROW_H];
// conv1 weights fp16: [kh][oc][18]
__device__ __half g_w1h[41 * 32 * 18];

// ---------------------------------------------------------------------------
__device__ __forceinline__ uint32_t smem_u32(const void* p) {
    uint32_t a;
    asm("{ .reg .u64 t; cvta.to.shared.u64 t, %1; cvt.u32.u64 %0, t; }"
        : "=r"(a) : "l"(p));
    return a;
}
__device__ __forceinline__ void cp16(uint32_t dst, const void* src) {
    asm volatile("cp.async.ca.shared.global [%0], [%1], 16;"
                 :: "r"(dst), "l"(src) : "memory");
}
__device__ __forceinline__ void cp_commit() {
    asm volatile("cp.async.commit_group;" ::: "memory");
}
__device__ __forceinline__ void cp_wait1() {
    asm volatile("cp.async.wait_group 1;" ::: "memory");
}
__device__ __forceinline__ void cp_wait0() {
    asm volatile("cp.async.wait_group 0;" ::: "memory");
}
__device__ __forceinline__ void ldm_x4(uint32_t* a, uint32_t addr) {
    asm volatile("ldmatrix.sync.aligned.m8n8.x4.shared.b16 {%0,%1,%2,%3}, [%4];"
                 : "=r"(a[0]), "=r"(a[1]), "=r"(a[2]), "=r"(a[3]) : "r"(addr));
}
__device__ __forceinline__ void mma_f16(float* d, const uint32_t* a,
                                        const uint32_t* b) {
    asm volatile(
        "mma.sync.aligned.m16n8k16.row.col.f32.f16.f16.f32 "
        "{%0,%1,%2,%3}, {%4,%5,%6,%7}, {%8,%9}, {%0,%1,%2,%3};"
        : "+f"(d[0]), "+f"(d[1]), "+f"(d[2]), "+f"(d[3])
        : "r"(a[0]), "r"(a[1]), "r"(a[2]), "r"(a[3]), "r"(b[0]), "r"(b[1]));
}

// ---------------------------------------------------------------------------
// Prep kernels
// ---------------------------------------------------------------------------
__global__ void prep_in_kernel(const float* __restrict__ in) {
    int i = blockIdx.x * 256 + threadIdx.x;
    const int total = BB * H0 * C1_ROW_H;
    if (i >= total) return;
    int t = i % C1_ROW_H;
    int r = i / C1_ROW_H;
    int s = t - 5;
    float v = 0.f;
    if ((unsigned)s < W0) v = in[(size_t)r * W0 + s];
    g_in_h[i] = __float2half_rn(v);
}

__global__ void prep_w1_kernel(const float* __restrict__ w1) {
    int i = blockIdx.x * 256 + threadIdx.x;
    const int total = 41 * 32 * 18;
    if (i >= total) return;
    int k = i % 18;
    int t = i / 18;
    int oc = t & 31;
    int kh = t >> 5;
    float v = (k < 11) ? w1[oc * 451 + kh * 11 + k] : 0.f;
    g_w1h[i] = __float2half_rn(v);
}

__global__ void transpose_w2_kernel(const float* __restrict__ w2) {
    int i = blockIdx.x * 256 + threadIdx.x;
    const int total = 21 * 11 * 32 * 40;
    if (i >= total) return;
    int ic = i % 40;
    int t = i / 40;
    int oc = t & 31;
    t >>= 5;
    int kw = t % 11;
    int kh = t / 11;
    float v = (ic < 32) ? w2[((oc * 32 + ic) * 21 + kh) * 11 + kw] : 0.f;
    g_w2h[i] = __float2half_rn(v);
}

// ---------------------------------------------------------------------------
// Kernel 1: conv1 via fp16 mma (unchanged, proven).
// ---------------------------------------------------------------------------
#define C1_HDR 256
#define C1_W_OFF C1_HDR
#define C1_W_BYTES (41 * 32 * 18 * 2)
#define C1_R_OFF (C1_W_OFF + C1_W_BYTES)
#define C1_ROWB (C1_ROW_H * 2)
#define C1_SM_BYTES (C1_R_OFF + 2 * C1_ROWB)

__global__ void __launch_bounds__(256, 2) conv1_mma_kernel(
    const int* __restrict__ seq,
    const float* __restrict__ b1, const float* __restrict__ g1,
    const float* __restrict__ be1, const float* __restrict__ m1,
    const float* __restrict__ v1)
{
    extern __shared__ char smc[];
    uint32_t sb = smem_u32(smc);
    float* hdr = (float*)smc;
    int tid = threadIdx.x, wid = tid >> 5, lane = tid & 31;
    int gid = lane >> 2, tg = lane & 3;
    int h1 = blockIdx.x, b = blockIdx.y;
    int len1 = (seq[b] - 1) / 2 + 1;
    int npix = min(512, len1);

    if (tid < 32) {
        float a = g1[tid] * rsqrtf(v1[tid] + EPSV);
        hdr[tid]      = a;
        hdr[32 + tid] = b1[tid] * a + be1[tid] - m1[tid] * a;
    }
    for (int i = tid; i < C1_W_BYTES / 16; i += 256)
        cp16(sb + C1_W_OFF + i * 16, (const char*)g_w1h + i * 16);
    cp_commit();

    int khL = max(0, 20 - 2 * h1);
    int khH = min(40, 180 - 2 * h1);
    const __half* inb = g_in_h + (size_t)(b * H0) * C1_ROW_H;

    auto load_row = [&](int kh, int buf) {
        const __half* src = inb + (size_t)(2 * h1 + kh - 20) * C1_ROW_H;
        uint32_t dst = sb + C1_R_OFF + buf * C1_ROWB;
        for (int i = tid; i < C1_ROWB / 16; i += 256)
            cp16(dst + i * 16, src + i * 8);
    };

    float acc[4][4][4];
#pragma unroll
    for (int mt = 0; mt < 4; mt++)
#pragma unroll
        for (int nt = 0; nt < 4; nt++)
#pragma unroll
            for (int r = 0; r < 4; r++) acc[mt][nt][r] = 0.f;

    load_row(khL, 0);
    cp_commit();
    int buf = 0;

    for (int kh = khL; kh <= khH; kh++) {
        if (kh < khH) {
            load_row(kh + 1, buf ^ 1);
            cp_commit();
            cp_wait1();
        } else {
            cp_wait0();
        }
        __syncthreads();

        uint32_t bf[4][2];
        const char* wk = smc + C1_W_OFF + kh * (32 * 18 * 2);
#pragma unroll
        for (int nt = 0; nt < 4; nt++) {
            const char* q = wk + (nt * 8 + gid) * 36 + tg * 4;
            bf[nt][0] = *(const uint32_t*)q;
            bf[nt][1] = *(const uint32_t*)(q + 16);
        }
        const char* arow = smc + C1_R_OFF + buf * C1_ROWB;
#pragma unroll
        for (int mt = 0; mt < 4; mt++) {
            int pb = wid * 64 + mt * 16;
            if (pb >= npix) continue;
            const char* ab = arow + 4 * (pb + gid + tg);
            uint32_t af[4];
            af[0] = *(const uint32_t*)(ab);
            af[1] = *(const uint32_t*)(ab + 32);
            af[2] = *(const uint32_t*)(ab + 16);
            af[3] = *(const uint32_t*)(ab + 48);
#pragma unroll
            for (int nt = 0; nt < 4; nt++)
                mma_f16(acc[mt][nt], af, bf[nt]);
        }
        __syncthreads();
        buf ^= 1;
    }

    const float* sa = hdr;
    const float* sc = hdr + 32;
    __half* xb = g_x1h + (size_t)(b * H1 + h1) * W1 * 32;
#pragma unroll
    for (int mt = 0; mt < 4; mt++) {
        int p0 = wid * 64 + mt * 16 + gid;
        int p1 = p0 + 8;
#pragma unroll
        for (int nt = 0; nt < 4; nt++) {
            int oc0 = nt * 8 + 2 * tg;
            float a0 = sa[oc0], c0 = sc[oc0];
            float a1 = sa[oc0 + 1], c1 = sc[oc0 + 1];
            float y0 = 0.f, y1 = 0.f, y2 = 0.f, y3 = 0.f;
            if (p0 < len1) {
                y0 = fminf(fmaxf(acc[mt][nt][0] * a0 + c0, 0.f), 20.f);
                y1 = fminf(fmaxf(acc[mt][nt][1] * a1 + c1, 0.f), 20.f);
            }
            if (p1 < len1) {
                y2 = fminf(fmaxf(acc[mt][nt][2] * a0 + c0, 0.f), 20.f);
                y3 = fminf(fmaxf(acc[mt][nt][3] * a1 + c1, 0.f), 20.f);
            }
            *(__half2*)(xb + (size_t)p0 * 32 + oc0) =
                __halves2half2(__float2half_rn(y0), __float2half_rn(y1));
            *(__half2*)(xb + (size_t)p1 * 32 + oc0) =
                __halves2half2(__float2half_rn(y2), __float2half_rn(y3));
        }
    }
}

// ---------------------------------------------------------------------------
// Kernel 2: conv2 fp16 mma implicit GEMM. CTA = (half-row 256 px, h2, b),
// 2 CTAs/SM, double-buffered, whole-CTA mask skip. Side-aware halo:
//   row r <-> pixel w0 + r - 5.
//   w0==0  : rows 0..4 zeroed (w<0), loads cover 5..r_hi (r_hi<=266).
//   w0==256: rows 0..4 LOADED from global (left halo), rows 261..265 zeroed
//            (w>=512), r_hi<=261. Zero loop never touches loaded rows.
// ---------------------------------------------------------------------------
#define HDR_B 256
#define A_STRIDE_B 80
#define A_ROWS2 266
#define ABUF_B (A_ROWS2 * A_STRIDE_B)   // 21280
#define BBUF_B (11 * 32 * 40 * 2)       // 28160
#define A0_OFF HDR_B
#define A1_OFF (A0_OFF + ABUF_B)
#define B0_OFF (A1_OFF + ABUF_B)
#define B1_OFF (B0_OFF + BBUF_B)
#define SM2_BYTES (B1_OFF + BBUF_B)     // 99136

__global__ void __launch_bounds__(256, 2) conv2_mma_kernel(
    const int* __restrict__ seq,
    const float* __restrict__ b2, const float* __restrict__ g2,
    const float* __restrict__ be2, const float* __restrict__ m2,
    const float* __restrict__ v2,
    float* __restrict__ out)
{
    extern __shared__ char smc[];
    uint32_t sb = smem_u32(smc);
    float* hdr = (float*)smc;
    int tid = threadIdx.x, wid = tid >> 5, lane = tid & 31;
    int gid = lane >> 2, tg = lane & 3;
    int w0 = blockIdx.x * 256;
    int h2 = blockIdx.y, b = blockIdx.z;
    int len1 = (seq[b] - 1) / 2 + 1;
    int npix = min(256, len1 - w0);

    if (npix <= 0) {
        float* o = out + ((size_t)(b * 32) * H2 + h2) * W2 + w0 + tid;
#pragma unroll
        for (int oc = 0; oc < 32; oc++) o[(size_t)oc * (H2 * W2)] = 0.f;
        return;
    }

    if (tid < 32) {
        float a = g2[tid] * rsqrtf(v2[tid] + EPSV);
        hdr[tid]      = a;
        hdr[32 + tid] = b2[tid] * a + be2[tid] - m2[tid] * a;
    }

    int rlo;  // first row filled by load_A
    // Zero exactly the rows loads never write: 5 rows x 5 chunks x 2 buffers.
    if (w0 == 0) {
        rlo = 5;
        for (int i = tid; i < 50; i += 256) {
            int bi = i / 25, j = i % 25;
            int r = j / 5;                       // rows 0..4 (w<0)
            *(float4*)(smc + (bi ? A1_OFF : A0_OFF) + r * A_STRIDE_B + (j % 5) * 16) =
                make_float4(0.f, 0.f, 0.f, 0.f);
        }
    } else {
        rlo = 0;
        for (int i = tid; i < 50; i += 256) {
            int bi = i / 25, j = i % 25;
            int r = 261 + j / 5;                 // rows 261..265 (w>=512)
            *(float4*)(smc + (bi ? A1_OFF : A0_OFF) + r * A_STRIDE_B + (j % 5) * 16) =
                make_float4(0.f, 0.f, 0.f, 0.f);
        }
    }

    int act  = min(256, (npix + 15) & ~15);
    int r_hi = min(min(act + 10, 517 - w0), A_ROWS2);

    int khL = max(0, 10 - 2 * h2);
    int khH = min(20, 90 - 2 * h2);
    const __half* xbase = g_x1h + ((size_t)(b * H1) * W1 + (w0 - 5)) * 32;

    auto load_A = [&](int kh, uint32_t aoff) {
        int ih = 2 * h2 + kh - 10;
        const __half* src = xbase + (size_t)ih * W1 * 32;
        int chunks = (r_hi - rlo) * 4;
        for (int i = tid; i < chunks; i += 256) {
            int r = rlo + (i >> 2), c = i & 3;
            cp16(sb + aoff + r * A_STRIDE_B + c * 16, src + (size_t)r * 32 + c * 8);
        }
    };
    auto load_B = [&](int kh, uint32_t boff) {
        const __half* src = g_w2h + (size_t)kh * (11 * 32 * 40);
        for (int i = tid; i < 1760; i += 256)
            cp16(sb + boff + i * 16, src + i * 8);
    };

    float acc[2][4][4];
#pragma unroll
    for (int mt = 0; mt < 2; mt++)
#pragma unroll
        for (int nt = 0; nt < 4; nt++)
#pragma unroll
            for (int r = 0; r < 4; r++) acc[mt][nt][r] = 0.f;

    load_A(khL, A0_OFF);
    load_B(khL, B0_OFF);
    cp_commit();

    uint32_t lane_a = (uint32_t)((lane & 15) * A_STRIDE_B + (lane >> 4) * 16);
    int buf = 0;

    for (int kh = khL; kh <= khH; kh++) {
        if (kh < khH) {
            load_A(kh + 1, buf ? A0_OFF : A1_OFF);
            load_B(kh + 1, buf ? B0_OFF : B1_OFF);
            cp_commit();
            cp_wait1();
        } else {
            cp_wait0();
        }
        __syncthreads();

        uint32_t aoff = buf ? A1_OFF : A0_OFF;
        const __half* bp0 = (const __half*)(smc + (buf ? B1_OFF : B0_OFF));

        for (int kw = 0; kw < 11; kw++) {
            uint32_t bf[4][2][2];
            const __half* bp = bp0 + kw * 32 * 40;
#pragma unroll
            for (int nt = 0; nt < 4; nt++)
#pragma unroll
                for (int ks = 0; ks < 2; ks++) {
                    const __half* q = bp + (nt * 8 + gid) * 40 + ks * 16 + 2 * tg;
                    bf[nt][ks][0] = *(const uint32_t*)q;
                    bf[nt][ks][1] = *(const uint32_t*)(q + 8);
                }
#pragma unroll
            for (int mt = 0; mt < 2; mt++) {
                int pb = wid * 32 + mt * 16;
                if (pb >= npix) continue;
                uint32_t abase = sb + aoff + (uint32_t)(pb + kw) * A_STRIDE_B + lane_a;
#pragma unroll
                for (int ks = 0; ks < 2; ks++) {
                    uint32_t af[4];
                    ldm_x4(af, abase + ks * 32);
#pragma unroll
                    for (int nt = 0; nt < 4; nt++)
                        mma_f16(acc[mt][nt], af, bf[nt][ks]);
                }
            }
        }
        __syncthreads();
        buf ^= 1;
    }

    const float* sa = hdr;
    const float* sc = hdr + 32;
#pragma unroll
    for (int mt = 0; mt < 2; mt++) {
        int p0 = wid * 32 + mt * 16 + gid;
        int p1 = p0 + 8;
#pragma unroll
        for (int nt = 0; nt < 4; nt++) {
            int oc0 = nt * 8 + 2 * tg;
            int oc1 = oc0 + 1;
            float a0 = sa[oc0], c0 = sc[oc0];
            float a1 = sa[oc1], c1 = sc[oc1];
            float* o0 = out + ((size_t)(b * 32 + oc0) * H2 + h2) * W2 + w0;
            float* o1 = out + ((size_t)(b * 32 + oc1) * H2 + h2) * W2 + w0;
            o0[p0] = (p0 < npix) ? fminf(fmaxf(acc[mt][nt][0] * a0 + c0, 0.f), 20.f) : 0.f;
            o1[p0] = (p0 < npix) ? fminf(fmaxf(acc[mt][nt][1] * a1 + c1, 0.f), 20.f) : 0.f;
            o0[p1] = (p1 < npix) ? fminf(fmaxf(acc[mt][nt][2] * a0 + c0, 0.f), 20.f) : 0.f;
            o1[p1] = (p1 < npix) ? fminf(fmaxf(acc[mt][nt][3] * a1 + c1, 0.f), 20.f) : 0.f;
        }
    }
}

// ---------------------------------------------------------------------------
__global__ void tail_kernel(const int* __restrict__ seq, float* __restrict__ out,
                            int base) {
    int i = threadIdx.x;
    if (i < BB) {
        int len1 = (seq[i] - 1) / 2 + 1;
        out[base + i] = (float)len1;
    }
}

extern "C" void kernel_launch(void* const* d_in, const int* in_sizes, int n_in,
                              void* d_out, int out_size) {
    const float* inputs = (const float*)d_in[0];
    const int*   seq    = (const int*)d_in[1];
    const float* w1 = (const float*)d_in[2];
    const float* b1 = (const float*)d_in[3];
    const float* g1 = (const float*)d_in[4];
    const float* be1 = (const float*)d_in[5];
    const float* m1 = (const float*)d_in[6];
    const float* v1 = (const float*)d_in[7];
    const float* w2 = (const float*)d_in[8];
    const float* b2 = (const float*)d_in[9];
    const float* g2 = (const float*)d_in[10];
    const float* be2 = (const float*)d_in[11];
    const float* m2 = (const float*)d_in[12];
    const float* v2 = (const float*)d_in[13];
    float* out = (float*)d_out;

    cudaFuncSetAttribute(conv1_mma_kernel, cudaFuncAttributeMaxDynamicSharedMemorySize, C1_SM_BYTES);
    cudaFuncSetAttribute(conv2_mma_kernel, cudaFuncAttributeMaxDynamicSharedMemorySize, SM2_BYTES);

    {
        int total = BB * H0 * C1_ROW_H;
        prep_in_kernel<<<(total + 255) / 256, 256>>>(inputs);
    }
    {
        int total = 41 * 32 * 18;
        prep_w1_kernel<<<(total + 255) / 256, 256>>>(w1);
    }
    {
        int total = 21 * 11 * 32 * 40;
        transpose_w2_kernel<<<(total + 255) / 256, 256>>>(w2);
    }
    {
        dim3 grid(H1, BB);
        conv1_mma_kernel<<<grid, 256, C1_SM_BYTES>>>(seq, b1, g1, be1, m1, v1);
    }
    {
        dim3 grid(2, H2, BB);
        conv2_mma_kernel<<<grid, 256, SM2_BYTES>>>(seq, b2, g2, be2, m2, v2, out);
    }
    const int xsize = BB * 32 * H2 * W2;
    if (out_size >= xsize + BB) {
        tail_kernel<<<1, 32>>>(seq, out, xsize);
    }
}

// round 8
// speedup vs baseline: 8.9478x; 1.0847x over previous
#include <cuda_runtime.h>
#include <cuda_fp16.h>
#include <math.h>
#include <stdint.h>

#define BB 32
#define H0 161
#define W0 1024
#define H1 81
#define W1 512
#define H2 41
#define W2 512
#define EPSV 1e-5f

// x1 scratch: channels-last fp16 [b][h1][w][ic]
__device__ __half g_x1h[BB * H1 * W1 * 32];
// conv2 weights fp16: [kh][kw][oc][40 pad]
__device__ __half g_w2h[21 * 11 * 32 * 40];
// conv1 input, fp16, shifted rows: [b][ih][t], t in [0,1056), S[t]=in[t-5]
#define C1_ROW_H 1056
__device__ __half g_in_h[BB * H0 * C1_ROW_H];
// conv1 weights fp16: [kh][oc][18]
__device__ __half g_w1h[41 * 32 * 18];

// ---------------------------------------------------------------------------
__device__ __forceinline__ uint32_t smem_u32(const void* p) {
    uint32_t a;
    asm("{ .reg .u64 t; cvta.to.shared.u64 t, %1; cvt.u32.u64 %0, t; }"
        : "=r"(a) : "l"(p));
    return a;
}
__device__ __forceinline__ void cp16(uint32_t dst, const void* src) {
    asm volatile("cp.async.ca.shared.global [%0], [%1], 16;"
                 :: "r"(dst), "l"(src) : "memory");
}
__device__ __forceinline__ void cp_commit() {
    asm volatile("cp.async.commit_group;" ::: "memory");
}
__device__ __forceinline__ void cp_wait1() {
    asm volatile("cp.async.wait_group 1;" ::: "memory");
}
__device__ __forceinline__ void cp_wait0() {
    asm volatile("cp.async.wait_group 0;" ::: "memory");
}
__device__ __forceinline__ void ldm_x4(uint32_t* a, uint32_t addr) {
    asm volatile("ldmatrix.sync.aligned.m8n8.x4.shared.b16 {%0,%1,%2,%3}, [%4];"
                 : "=r"(a[0]), "=r"(a[1]), "=r"(a[2]), "=r"(a[3]) : "r"(addr));
}
__device__ __forceinline__ void mma_f16(float* d, const uint32_t* a,
                                        const uint32_t* b) {
    asm volatile(
        "mma.sync.aligned.m16n8k16.row.col.f32.f16.f16.f32 "
        "{%0,%1,%2,%3}, {%4,%5,%6,%7}, {%8,%9}, {%0,%1,%2,%3};"
        : "+f"(d[0]), "+f"(d[1]), "+f"(d[2]), "+f"(d[3])
        : "r"(a[0]), "r"(a[1]), "r"(a[2]), "r"(a[3]), "r"(b[0]), "r"(b[1]));
}

// ---------------------------------------------------------------------------
// Prep kernels
// ---------------------------------------------------------------------------
__global__ void prep_in_kernel(const float* __restrict__ in) {
    int i = blockIdx.x * 256 + threadIdx.x;
    const int total = BB * H0 * C1_ROW_H;
    if (i >= total) return;
    int t = i % C1_ROW_H;
    int r = i / C1_ROW_H;
    int s = t - 5;
    float v = 0.f;
    if ((unsigned)s < W0) v = in[(size_t)r * W0 + s];
    g_in_h[i] = __float2half_rn(v);
}

__global__ void prep_w1_kernel(const float* __restrict__ w1) {
    int i = blockIdx.x * 256 + threadIdx.x;
    const int total = 41 * 32 * 18;
    if (i >= total) return;
    int k = i % 18;
    int t = i / 18;
    int oc = t & 31;
    int kh = t >> 5;
    float v = (k < 11) ? w1[oc * 451 + kh * 11 + k] : 0.f;
    g_w1h[i] = __float2half_rn(v);
}

__global__ void transpose_w2_kernel(const float* __restrict__ w2) {
    int i = blockIdx.x * 256 + threadIdx.x;
    const int total = 21 * 11 * 32 * 40;
    if (i >= total) return;
    int ic = i % 40;
    int t = i / 40;
    int oc = t & 31;
    t >>= 5;
    int kw = t % 11;
    int kh = t / 11;
    float v = (ic < 32) ? w2[((oc * 32 + ic) * 21 + kh) * 11 + kw] : 0.f;
    g_w2h[i] = __float2half_rn(v);
}

// ---------------------------------------------------------------------------
// Kernel 1: conv1 fp16 mma, barrier-free mainloop. w1 slab in smem (loaded
// once); A-fragments loaded straight from g_in_h (L1-resident rows).
// CTA = (h1, b): 8 warps x 64 px, 4 mtiles/warp.
// ---------------------------------------------------------------------------
#define C1_HDR 256
#define C1_W_OFF C1_HDR
#define C1_W_BYTES (41 * 32 * 18 * 2)
#define C1_SM_BYTES (C1_W_OFF + C1_W_BYTES)   // 47488

__global__ void __launch_bounds__(256, 2) conv1_mma_kernel(
    const int* __restrict__ seq,
    const float* __restrict__ b1, const float* __restrict__ g1,
    const float* __restrict__ be1, const float* __restrict__ m1,
    const float* __restrict__ v1)
{
    extern __shared__ char smc[];
    uint32_t sb = smem_u32(smc);
    float* hdr = (float*)smc;
    int tid = threadIdx.x, wid = tid >> 5, lane = tid & 31;
    int gid = lane >> 2, tg = lane & 3;
    int h1 = blockIdx.x, b = blockIdx.y;
    int len1 = (seq[b] - 1) / 2 + 1;
    int npix = min(512, len1);

    if (tid < 32) {
        float a = g1[tid] * rsqrtf(v1[tid] + EPSV);
        hdr[tid]      = a;
        hdr[32 + tid] = b1[tid] * a + be1[tid] - m1[tid] * a;
    }
    for (int i = tid; i < C1_W_BYTES / 16; i += 256)
        cp16(sb + C1_W_OFF + i * 16, (const char*)g_w1h + i * 16);
    cp_commit();
    cp_wait0();
    __syncthreads();   // the ONLY pre-epilogue barrier

    int khL = max(0, 20 - 2 * h1);
    int khH = min(40, 180 - 2 * h1);
    const char* inb =
        (const char*)(g_in_h + (size_t)(b * H0 + 2 * h1 - 20) * C1_ROW_H);

    float acc[4][4][4];
#pragma unroll
    for (int mt = 0; mt < 4; mt++)
#pragma unroll
        for (int nt = 0; nt < 4; nt++)
#pragma unroll
            for (int r = 0; r < 4; r++) acc[mt][nt][r] = 0.f;

    int lofs = 4 * (gid + tg);   // lane word offset within a row

#pragma unroll 2
    for (int kh = khL; kh <= khH; kh++) {
        // B frags from smem w1 slab
        uint32_t bf[4][2];
        const char* wk = smc + C1_W_OFF + kh * (32 * 18 * 2);
#pragma unroll
        for (int nt = 0; nt < 4; nt++) {
            const char* q = wk + (nt * 8 + gid) * 36 + tg * 4;
            bf[nt][0] = *(const uint32_t*)q;
            bf[nt][1] = *(const uint32_t*)(q + 16);
        }
        const char* arow = inb + (size_t)kh * (C1_ROW_H * 2);
#pragma unroll
        for (int mt = 0; mt < 4; mt++) {
            int pb = wid * 64 + mt * 16;
            if (pb >= npix) continue;
            const char* ab = arow + 4 * pb + lofs;
            uint32_t af[4];
            af[0] = *(const uint32_t*)(ab);
            af[1] = *(const uint32_t*)(ab + 32);
            af[2] = *(const uint32_t*)(ab + 16);
            af[3] = *(const uint32_t*)(ab + 48);
#pragma unroll
            for (int nt = 0; nt < 4; nt++)
                mma_f16(acc[mt][nt], af, bf[nt]);
        }
    }

    const float* sa = hdr;
    const float* sc = hdr + 32;
    __half* xb = g_x1h + (size_t)(b * H1 + h1) * W1 * 32;
#pragma unroll
    for (int mt = 0; mt < 4; mt++) {
        int p0 = wid * 64 + mt * 16 + gid;
        int p1 = p0 + 8;
#pragma unroll
        for (int nt = 0; nt < 4; nt++) {
            int oc0 = nt * 8 + 2 * tg;
            float a0 = sa[oc0], c0 = sc[oc0];
            float a1 = sa[oc0 + 1], c1 = sc[oc0 + 1];
            float y0 = 0.f, y1 = 0.f, y2 = 0.f, y3 = 0.f;
            if (p0 < len1) {
                y0 = fminf(fmaxf(acc[mt][nt][0] * a0 + c0, 0.f), 20.f);
                y1 = fminf(fmaxf(acc[mt][nt][1] * a1 + c1, 0.f), 20.f);
            }
            if (p1 < len1) {
                y2 = fminf(fmaxf(acc[mt][nt][2] * a0 + c0, 0.f), 20.f);
                y3 = fminf(fmaxf(acc[mt][nt][3] * a1 + c1, 0.f), 20.f);
            }
            *(__half2*)(xb + (size_t)p0 * 32 + oc0) =
                __halves2half2(__float2half_rn(y0), __float2half_rn(y1));
            *(__half2*)(xb + (size_t)p1 * 32 + oc0) =
                __halves2half2(__float2half_rn(y2), __float2half_rn(y3));
        }
    }
}

// ---------------------------------------------------------------------------
// Kernel 2: conv2 fp16 mma implicit GEMM. CTA = (half-row 256 px, h2, b),
// 2 CTAs/SM, double-buffered, whole-CTA mask skip, side-aware halo.
// B-fragments now via ldmatrix.x4 (tile (nt; ks,h): row=oc, cols=k halves).
// ---------------------------------------------------------------------------
#define HDR_B 256
#define A_STRIDE_B 80
#define A_ROWS2 266
#define ABUF_B (A_ROWS2 * A_STRIDE_B)
#define BBUF_B (11 * 32 * 40 * 2)
#define A0_OFF HDR_B
#define A1_OFF (A0_OFF + ABUF_B)
#define B0_OFF (A1_OFF + ABUF_B)
#define B1_OFF (B0_OFF + BBUF_B)
#define SM2_BYTES (B1_OFF + BBUF_B)     // 99136

__global__ void __launch_bounds__(256, 2) conv2_mma_kernel(
    const int* __restrict__ seq,
    const float* __restrict__ b2, const float* __restrict__ g2,
    const float* __restrict__ be2, const float* __restrict__ m2,
    const float* __restrict__ v2,
    float* __restrict__ out)
{
    extern __shared__ char smc[];
    uint32_t sb = smem_u32(smc);
    float* hdr = (float*)smc;
    int tid = threadIdx.x, wid = tid >> 5, lane = tid & 31;
    int gid = lane >> 2, tg = lane & 3;
    int w0 = blockIdx.x * 256;
    int h2 = blockIdx.y, b = blockIdx.z;
    int len1 = (seq[b] - 1) / 2 + 1;
    int npix = min(256, len1 - w0);

    if (npix <= 0) {
        float* o = out + ((size_t)(b * 32) * H2 + h2) * W2 + w0 + tid;
#pragma unroll
        for (int oc = 0; oc < 32; oc++) o[(size_t)oc * (H2 * W2)] = 0.f;
        return;
    }

    if (tid < 32) {
        float a = g2[tid] * rsqrtf(v2[tid] + EPSV);
        hdr[tid]      = a;
        hdr[32 + tid] = b2[tid] * a + be2[tid] - m2[tid] * a;
    }

    int rlo;
    if (w0 == 0) {
        rlo = 5;
        for (int i = tid; i < 50; i += 256) {
            int bi = i / 25, j = i % 25;
            int r = j / 5;
            *(float4*)(smc + (bi ? A1_OFF : A0_OFF) + r * A_STRIDE_B + (j % 5) * 16) =
                make_float4(0.f, 0.f, 0.f, 0.f);
        }
    } else {
        rlo = 0;
        for (int i = tid; i < 50; i += 256) {
            int bi = i / 25, j = i % 25;
            int r = 261 + j / 5;
            *(float4*)(smc + (bi ? A1_OFF : A0_OFF) + r * A_STRIDE_B + (j % 5) * 16) =
                make_float4(0.f, 0.f, 0.f, 0.f);
        }
    }

    int act  = min(256, (npix + 15) & ~15);
    int r_hi = min(min(act + 10, 517 - w0), A_ROWS2);

    int khL = max(0, 10 - 2 * h2);
    int khH = min(20, 90 - 2 * h2);
    const __half* xbase = g_x1h + ((size_t)(b * H1) * W1 + (w0 - 5)) * 32;

    auto load_A = [&](int kh, uint32_t aoff) {
        int ih = 2 * h2 + kh - 10;
        const __half* src = xbase + (size_t)ih * W1 * 32;
        int chunks = (r_hi - rlo) * 4;
        for (int i = tid; i < chunks; i += 256) {
            int r = rlo + (i >> 2), c = i & 3;
            cp16(sb + aoff + r * A_STRIDE_B + c * 16, src + (size_t)r * 32 + c * 8);
        }
    };
    auto load_B = [&](int kh, uint32_t boff) {
        const __half* src = g_w2h + (size_t)kh * (11 * 32 * 40);
        for (int i = tid; i < 1760; i += 256)
            cp16(sb + boff + i * 16, src + i * 8);
    };

    float acc[2][4][4];
#pragma unroll
    for (int mt = 0; mt < 2; mt++)
#pragma unroll
        for (int nt = 0; nt < 4; nt++)
#pragma unroll
            for (int r = 0; r < 4; r++) acc[mt][nt][r] = 0.f;

    load_A(khL, A0_OFF);
    load_B(khL, B0_OFF);
    cp_commit();

    uint32_t lane_a = (uint32_t)((lane & 15) * A_STRIDE_B + (lane >> 4) * 16);
    // ldmatrix lane base for B: tile j = lane/8 -> (ks=j/2, h=j&1); row = lane%8.
    uint32_t lane_b = (uint32_t)((lane & 7) * A_STRIDE_B +
                                 ((lane >> 4) * 32) + (((lane >> 3) & 1) * 16));
    int buf = 0;

    for (int kh = khL; kh <= khH; kh++) {
        if (kh < khH) {
            load_A(kh + 1, buf ? A0_OFF : A1_OFF);
            load_B(kh + 1, buf ? B0_OFF : B1_OFF);
            cp_commit();
            cp_wait1();
        } else {
            cp_wait0();
        }
        __syncthreads();

        uint32_t aoff = buf ? A1_OFF : A0_OFF;
        uint32_t bB = sb + (buf ? B1_OFF : B0_OFF) + lane_b;

        for (int kw = 0; kw < 11; kw++) {
            // B frags via ldmatrix: call nt -> regs [ks0h0, ks0h1, ks1h0, ks1h1]
            uint32_t bfr[4][4];
            uint32_t bkw = bB + (uint32_t)kw * 2560;
#pragma unroll
            for (int nt = 0; nt < 4; nt++)
                ldm_x4(bfr[nt], bkw + nt * 640);
#pragma unroll
            for (int mt = 0; mt < 2; mt++) {
                int pb = wid * 32 + mt * 16;
                if (pb >= npix) continue;
                uint32_t abase = sb + aoff + (uint32_t)(pb + kw) * A_STRIDE_B + lane_a;
#pragma unroll
                for (int ks = 0; ks < 2; ks++) {
                    uint32_t af[4];
                    ldm_x4(af, abase + ks * 32);
#pragma unroll
                    for (int nt = 0; nt < 4; nt++)
                        mma_f16(acc[mt][nt], af, &bfr[nt][2 * ks]);
                }
            }
        }
        __syncthreads();
        buf ^= 1;
    }

    const float* sa = hdr;
    const float* sc = hdr + 32;
#pragma unroll
    for (int mt = 0; mt < 2; mt++) {
        int p0 = wid * 32 + mt * 16 + gid;
        int p1 = p0 + 8;
#pragma unroll
        for (int nt = 0; nt < 4; nt++) {
            int oc0 = nt * 8 + 2 * tg;
            int oc1 = oc0 + 1;
            float a0 = sa[oc0], c0 = sc[oc0];
            float a1 = sa[oc1], c1 = sc[oc1];
            float* o0 = out + ((size_t)(b * 32 + oc0) * H2 + h2) * W2 + w0;
            float* o1 = out + ((size_t)(b * 32 + oc1) * H2 + h2) * W2 + w0;
            o0[p0] = (p0 < npix) ? fminf(fmaxf(acc[mt][nt][0] * a0 + c0, 0.f), 20.f) : 0.f;
            o1[p0] = (p0 < npix) ? fminf(fmaxf(acc[mt][nt][1] * a1 + c1, 0.f), 20.f) : 0.f;
            o0[p1] = (p1 < npix) ? fminf(fmaxf(acc[mt][nt][2] * a0 + c0, 0.f), 20.f) : 0.f;
            o1[p1] = (p1 < npix) ? fminf(fmaxf(acc[mt][nt][3] * a1 + c1, 0.f), 20.f) : 0.f;
        }
    }
}

// ---------------------------------------------------------------------------
__global__ void tail_kernel(const int* __restrict__ seq, float* __restrict__ out,
                            int base) {
    int i = threadIdx.x;
    if (i < BB) {
        int len1 = (seq[i] - 1) / 2 + 1;
        out[base + i] = (float)len1;
    }
}

extern "C" void kernel_launch(void* const* d_in, const int* in_sizes, int n_in,
                              void* d_out, int out_size) {
    const float* inputs = (const float*)d_in[0];
    const int*   seq    = (const int*)d_in[1];
    const float* w1 = (const float*)d_in[2];
    const float* b1 = (const float*)d_in[3];
    const float* g1 = (const float*)d_in[4];
    const float* be1 = (const float*)d_in[5];
    const float* m1 = (const float*)d_in[6];
    const float* v1 = (const float*)d_in[7];
    const float* w2 = (const float*)d_in[8];
    const float* b2 = (const float*)d_in[9];
    const float* g2 = (const float*)d_in[10];
    const float* be2 = (const float*)d_in[11];
    const float* m2 = (const float*)d_in[12];
    const float* v2 = (const float*)d_in[13];
    float* out = (float*)d_out;

    cudaFuncSetAttribute(conv1_mma_kernel, cudaFuncAttributeMaxDynamicSharedMemorySize, C1_SM_BYTES);
    cudaFuncSetAttribute(conv2_mma_kernel, cudaFuncAttributeMaxDynamicSharedMemorySize, SM2_BYTES);

    {
        int total = BB * H0 * C1_ROW_H;
        prep_in_kernel<<<(total + 255) / 256, 256>>>(inputs);
    }
    {
        int total = 41 * 32 * 18;
        prep_w1_kernel<<<(total + 255) / 256, 256>>>(w1);
    }
    {
        int total = 21 * 11 * 32 * 40;
        transpose_w2_kernel<<<(total + 255) / 256, 256>>>(w2);
    }
    {
        dim3 grid(H1, BB);
        conv1_mma_kernel<<<grid, 256, C1_SM_BYTES>>>(seq, b1, g1, be1, m1, v1);
    }
    {
        dim3 grid(2, H2, BB);
        conv2_mma_kernel<<<grid, 256, SM2_BYTES>>>(seq, b2, g2, be2, m2, v2, out);
    }
    const int xsize = BB * 32 * H2 * W2;
    if (out_size >= xsize + BB) {
        tail_kernel<<<1, 32>>>(seq, out, xsize);
    }
}